// round 14
// baseline (speedup 1.0000x reference)
#include <cuda_runtime.h>
#include <cuda_pipeline.h>
#include <cuda_fp16.h>
#include <cstdint>

// Problem constants
#define CB   4
#define CN   16384
#define CD   128
#define CP   100
#define CKP  112         // K padding for combine (7 k16-steps)
#define CBN  (CB * CN)   // 65536 points

// ---------------------------------------------------------------------------
// Scratch (static __device__ arrays; .bss zeroed — pad regions stay zero)
// ---------------------------------------------------------------------------
__device__ __align__(16) __half g_xproj[(size_t)CP * CBN];  // x projections; later diff
__device__ __align__(16) __half g_yproj[(size_t)CP * CBN];  // y projections
__device__ __align__(16) __half g_thetaH[128 * CD];         // [p][d], rows p>=100 == 0
__device__ __align__(16) __half g_thetaTH[CD * 128];        // [d][p], cols p>=100 == 0

// ---------------------------------------------------------------------------
// PTX helpers
// ---------------------------------------------------------------------------
__device__ __forceinline__ uint32_t smem_u32(const void* p) {
    uint32_t a;
    asm("{ .reg .u64 t; cvta.to.shared.u64 t, %1; cvt.u32.u64 %0, t; }" : "=r"(a) : "l"(p));
    return a;
}
// m16n8k16 fp16 MMA, fp32 accumulate
__device__ __forceinline__ void mma_f16(float* d, const uint32_t* a, const uint32_t* b) {
    asm volatile(
        "mma.sync.aligned.m16n8k16.row.col.f32.f16.f16.f32 "
        "{%0,%1,%2,%3}, {%4,%5,%6,%7}, {%8,%9}, {%0,%1,%2,%3};"
        : "+f"(d[0]), "+f"(d[1]), "+f"(d[2]), "+f"(d[3])
        : "r"(a[0]), "r"(a[1]), "r"(a[2]), "r"(a[3]), "r"(b[0]), "r"(b[1]));
}
__device__ __forceinline__ void ldm_x4(uint32_t* d, uint32_t addr) {
    asm volatile("ldmatrix.sync.aligned.m8n8.x4.shared.b16 {%0,%1,%2,%3}, [%4];"
        : "=r"(d[0]), "=r"(d[1]), "=r"(d[2]), "=r"(d[3]) : "r"(addr));
}
__device__ __forceinline__ void ldm_x4_trans(uint32_t* d, uint32_t addr) {
    asm volatile("ldmatrix.sync.aligned.m8n8.x4.trans.shared.b16 {%0,%1,%2,%3}, [%4];"
        : "=r"(d[0]), "=r"(d[1]), "=r"(d[2]), "=r"(d[3]) : "r"(addr));
}

// Monotone 12-bit quantizer: 4096 bins over [-8, 8].
__device__ __forceinline__ int quant12(float v) {
    int q = __float2int_rn(fmaf(v, 256.0f, 2048.0f));
    return max(0, min(4095, q));
}
__device__ __forceinline__ unsigned int warp_incl_scan(unsigned int v) {
#pragma unroll
    for (int o = 1; o < 32; o <<= 1) {
        unsigned int n = __shfl_up_sync(0xffffffffu, v, o);
        if ((threadIdx.x & 31) >= o) v += n;
    }
    return v;
}

#define ST 136   // smem row stride in halves: 272B rows -> ldmatrix conflict-free

// ---------------------------------------------------------------------------
// Kernel 1: normalize theta; emit [p][d] (proj B) and [d][p] (combine B) fp16.
// ---------------------------------------------------------------------------
__global__ void norm_kernel(const float* __restrict__ th) {
    int p = blockIdx.x, d = threadIdx.x;
    float v  = th[p * CD + d];
    float ss = v * v;
#pragma unroll
    for (int o = 16; o; o >>= 1) ss += __shfl_xor_sync(0xffffffffu, ss, o);
    __shared__ float ws[4];
    if ((d & 31) == 0) ws[d >> 5] = ss;
    __syncthreads();
    float tot = ws[0] + ws[1] + ws[2] + ws[3];
    __half h = __float2half(v / fmaxf(sqrtf(tot), 1e-12f));
    g_thetaH[p * CD + d]   = h;
    g_thetaTH[d * 128 + p] = h;
}

// ---------------------------------------------------------------------------
// Kernel 2: projections, fp16 m16n8k16 with ldmatrix fragment loads.
// Tile: D[m(128) x p(128)] = X . Theta^T. Warp grid 2(m) x 4(p); 8 k-steps;
// 6 ldmatrix + 16 MMA per k-step.
// ---------------------------------------------------------------------------
__global__ __launch_bounds__(256, 2) void proj_mma(const float* __restrict__ x,
                                                   const float* __restrict__ y) {
    extern __shared__ __align__(16) __half sm[];
    __half* sA = sm;             // X     [m][d]  128 x ST
    __half* sB = sm + 128 * ST;  // theta [p][d]  128 x ST
    const float* __restrict__ src = blockIdx.y ? y : x;
    __half* __restrict__ dst      = blockIdx.y ? g_yproj : g_xproj;
    const int m0 = blockIdx.x * 128;
    const int t = threadIdx.x;

    // theta via cp.async (already fp16 in gmem); fire first
#pragma unroll
    for (int j = 0; j < 8; j++) {
        int i = t + 256 * j, r = i >> 4, c = i & 15;
        __pipeline_memcpy_async((char*)(sB + r * ST) + c * 16,
                                (const char*)(g_thetaH + r * CD) + c * 16, 16);
    }
    __pipeline_commit();
    // X with inline f32 -> f16 conversion
#pragma unroll
    for (int j = 0; j < 16; j++) {
        int i = t + 256 * j, r = i >> 5, c = i & 31;
        float4 v = *reinterpret_cast<const float4*>(src + (size_t)(m0 + r) * CD + c * 4);
        *reinterpret_cast<__half2*>(sA + r * ST + c * 4)     = __floats2half2_rn(v.x, v.y);
        *reinterpret_cast<__half2*>(sA + r * ST + c * 4 + 2) = __floats2half2_rn(v.z, v.w);
    }
    __pipeline_wait_prior(0);
    __syncthreads();

    const int w = t >> 5, lane = t & 31;
    const int wm = (w >> 2) * 64, wn = (w & 3) * 32;
    const int grp = lane >> 2, tig = lane & 3;
    const int q = lane >> 3, rr = lane & 7;

    // per-lane ldmatrix base addresses (bytes)
    const uint32_t sAu = smem_u32(sA), sBu = smem_u32(sB);
    uint32_t aAddr[4], bAddr[2];
#pragma unroll
    for (int ma = 0; ma < 4; ma++)
        aAddr[ma] = sAu + ((wm + ma * 16 + (q & 1) * 8 + rr) * ST + (q >> 1) * 8) * 2;
#pragma unroll
    for (int pr = 0; pr < 2; pr++)
        bAddr[pr] = sBu + ((wn + pr * 16 + (q >> 1) * 8 + rr) * ST + (q & 1) * 8) * 2;

    float acc[4][4][4];
#pragma unroll
    for (int i = 0; i < 4; i++)
#pragma unroll
        for (int j = 0; j < 4; j++)
#pragma unroll
            for (int k = 0; k < 4; k++) acc[i][j][k] = 0.0f;

#pragma unroll
    for (int ks = 0; ks < 8; ks++) {
        uint32_t a[4][4], b[2][4];
#pragma unroll
        for (int ma = 0; ma < 4; ma++) ldm_x4(a[ma], aAddr[ma] + ks * 32);
#pragma unroll
        for (int pr = 0; pr < 2; pr++) ldm_x4(b[pr], bAddr[pr] + ks * 32);
#pragma unroll
        for (int ma = 0; ma < 4; ma++)
#pragma unroll
            for (int na = 0; na < 4; na++)
                mma_f16(acc[ma][na], a[ma], &b[na >> 1][(na & 1) * 2]);
    }

    // epilogue: D[m][p] -> dst[p*CBN + m] (half); skip pad cols p>=100
#pragma unroll
    for (int ma = 0; ma < 4; ma++) {
        int mg = m0 + wm + ma * 16 + grp;
#pragma unroll
        for (int na = 0; na < 4; na++) {
            int pp = wn + na * 8 + 2 * tig;
#pragma unroll
            for (int j = 0; j < 4; j++) {
                int p = pp + (j & 1);
                int m = mg + ((j >> 1) << 3);
                if (p < CP) dst[(size_t)p * CBN + m] = __float2half(acc[ma][na][j]);
            }
        }
    }
}

// ---------------------------------------------------------------------------
// Kernel 3: per-segment transport pairing via bucket/counting sort (12-bit),
// fp16 in/out.
// ---------------------------------------------------------------------------
#define NBIN 4096
struct SortSmem {
    unsigned int hx[NBIN];
    unsigned int hy[NBIN];
    __half       ysort[CN];
    unsigned int tmp[64];
};

__global__ __launch_bounds__(1024, 2) void sort_kernel() {
    extern __shared__ __align__(16) char smem_raw[];
    SortSmem& s = *reinterpret_cast<SortSmem*>(smem_raw);

    const int    t    = threadIdx.x;
    const int    lane = t & 31, wid = t >> 5;
    const size_t base = (size_t)blockIdx.x * CN;

#pragma unroll
    for (int i = t; i < NBIN; i += 1024) { s.hx[i] = 0; s.hy[i] = 0; }
    __syncthreads();

#pragma unroll
    for (int i = t; i < CN; i += 1024) {
        atomicAdd(&s.hx[quant12(__half2float(g_xproj[base + i]))], 1u);
        atomicAdd(&s.hy[quant12(__half2float(g_yproj[base + i]))], 1u);
    }
    __syncthreads();

    {   // dual in-place exclusive scan (4 bins per thread per histogram)
        const int b0 = t * 4;
        unsigned int ax[4], ay[4], sx = 0, sy = 0;
#pragma unroll
        for (int i = 0; i < 4; i++) {
            ax[i] = s.hx[b0 + i]; sx += ax[i];
            ay[i] = s.hy[b0 + i]; sy += ay[i];
        }
        unsigned int ix = warp_incl_scan(sx);
        unsigned int iy = warp_incl_scan(sy);
        if (lane == 31) { s.tmp[wid] = ix; s.tmp[32 + wid] = iy; }
        __syncthreads();
        if (wid == 0) {
            unsigned int vx = s.tmp[lane], vy = s.tmp[32 + lane];
            unsigned int jx = warp_incl_scan(vx), jy = warp_incl_scan(vy);
            s.tmp[lane]      = jx - vx;
            s.tmp[32 + lane] = jy - vy;
        }
        __syncthreads();
        unsigned int bx = s.tmp[wid] + ix - sx;
        unsigned int by = s.tmp[32 + wid] + iy - sy;
#pragma unroll
        for (int i = 0; i < 4; i++) {
            unsigned int c;
            c = ax[i]; s.hx[b0 + i] = bx; bx += c;
            c = ay[i]; s.hy[b0 + i] = by; by += c;
        }
    }
    __syncthreads();

#pragma unroll
    for (int i = t; i < CN; i += 1024) {
        __half yh = g_yproj[base + i];
        unsigned int r = atomicAdd(&s.hy[quant12(__half2float(yh))], 1u);
        s.ysort[r] = yh;
    }
    __syncthreads();

#pragma unroll
    for (int i = t; i < CN; i += 1024) {
        float xv = __half2float(g_xproj[base + i]);
        unsigned int r = atomicAdd(&s.hx[quant12(xv)], 1u);
        g_xproj[base + i] = __float2half(__half2float(s.ysort[r]) - xv);
    }
}

// ---------------------------------------------------------------------------
// Kernel 4: combine, fp16 m16n8k16 with ldmatrix.trans A loads.
// D[m(128) x d(128)] = diffT[m][p] . theta[p][d]; K = p padded to 112.
// diff staged in NATURAL [p][m] layout (pure cp.async, no transpose phase);
// ldmatrix.trans performs the transpose in the LDS unit.
// ---------------------------------------------------------------------------
__global__ __launch_bounds__(256, 2) void combine_mma(const float* __restrict__ x,
                                                      float* __restrict__ out) {
    extern __shared__ __align__(16) __half sm[];
    __half* sA = sm;             // diff   [p][m_local]  CKP x ST
    __half* sB = sm + CKP * ST;  // thetaT [d][p]        128 x ST
    const int m0 = blockIdx.x * 128;
    const int t = threadIdx.x;

    // diff rows p<100, natural layout, coalesced cp.async
    for (int i = t; i < CP * 16; i += 256) {
        int r = i >> 4, c = i & 15;
        __pipeline_memcpy_async((char*)(sA + r * ST) + c * 16,
                                (const char*)(g_xproj + (size_t)r * CBN + m0) + c * 16, 16);
    }
    // theta [d][p] rows
#pragma unroll
    for (int j = 0; j < 8; j++) {
        int i = t + 256 * j, r = i >> 4, c = i & 15;
        __pipeline_memcpy_async((char*)(sB + r * ST) + c * 16,
                                (const char*)(g_thetaTH + r * 128) + c * 16, 16);
    }
    __pipeline_commit();
    // zero diff pad rows p in [100,112): 12 rows x 16 chunks
    for (int i = t; i < 12 * 16; i += 256) {
        int r = CP + (i >> 4), c = i & 15;
        *reinterpret_cast<float4*>((char*)(sA + r * ST) + c * 16) =
            make_float4(0.f, 0.f, 0.f, 0.f);
    }
    __pipeline_wait_prior(0);
    __syncthreads();

    const int w = t >> 5, lane = t & 31;
    const int wm = (w >> 2) * 64, wn = (w & 3) * 32;
    const int grp = lane >> 2, tig = lane & 3;
    const int q = lane >> 3, rr = lane & 7;

    const uint32_t sAu = smem_u32(sA), sBu = smem_u32(sB);
    uint32_t aAddr[4], bAddr[2];
#pragma unroll
    for (int ma = 0; ma < 4; ma++)   // trans: rows are k(=p), cols are m
        aAddr[ma] = sAu + (((q >> 1) * 8 + rr) * ST + wm + ma * 16 + (q & 1) * 8) * 2;
#pragma unroll
    for (int pr = 0; pr < 2; pr++)
        bAddr[pr] = sBu + ((wn + pr * 16 + (q >> 1) * 8 + rr) * ST + (q & 1) * 8) * 2;

    float acc[4][4][4];
#pragma unroll
    for (int i = 0; i < 4; i++)
#pragma unroll
        for (int j = 0; j < 4; j++)
#pragma unroll
            for (int k = 0; k < 4; k++) acc[i][j][k] = 0.0f;

#pragma unroll
    for (int ks = 0; ks < 7; ks++) {
        uint32_t a[4][4], b[2][4];
#pragma unroll
        for (int ma = 0; ma < 4; ma++) ldm_x4_trans(a[ma], aAddr[ma] + ks * 16 * ST * 2);
#pragma unroll
        for (int pr = 0; pr < 2; pr++) ldm_x4(b[pr], bAddr[pr] + ks * 32);
#pragma unroll
        for (int ma = 0; ma < 4; ma++)
#pragma unroll
            for (int na = 0; na < 4; na++)
                mma_f16(acc[ma][na], a[ma], &b[na >> 1][(na & 1) * 2]);
    }

    // epilogue: out[m][d] = x[m][d] + sc*D[m][d], float2 stores
    const float sc = 1.0f / (float)CP;
#pragma unroll
    for (int ma = 0; ma < 4; ma++) {
#pragma unroll
        for (int j2 = 0; j2 < 2; j2++) {
            size_t row = (size_t)(m0 + wm + ma * 16 + grp + j2 * 8) * CD;
#pragma unroll
            for (int na = 0; na < 4; na++) {
                int d = wn + na * 8 + 2 * tig;
                float2 xv = *reinterpret_cast<const float2*>(&x[row + d]);
                float2 o  = make_float2(fmaf(acc[ma][na][j2 * 2],     sc, xv.x),
                                        fmaf(acc[ma][na][j2 * 2 + 1], sc, xv.y));
                *reinterpret_cast<float2*>(&out[row + d]) = o;
            }
        }
    }
}

// ---------------------------------------------------------------------------
// Entry point
// ---------------------------------------------------------------------------
extern "C" void kernel_launch(void* const* d_in, const int* in_sizes, int n_in,
                              void* d_out, int out_size) {
    const float* x   = (const float*)d_in[0];
    const float* y   = (const float*)d_in[1];
    const float* th  = (const float*)d_in[2];
    float*       out = (float*)d_out;

    const int proj_smem = 2 * 128 * ST * 2;        // 69,632 B
    const int comb_smem = (CKP + 128) * ST * 2;    // 65,280 B
    cudaFuncSetAttribute(sort_kernel, cudaFuncAttributeMaxDynamicSharedMemorySize,
                         (int)sizeof(SortSmem));
    cudaFuncSetAttribute(proj_mma, cudaFuncAttributeMaxDynamicSharedMemorySize, proj_smem);
    cudaFuncSetAttribute(combine_mma, cudaFuncAttributeMaxDynamicSharedMemorySize, comb_smem);

    norm_kernel<<<CP, CD>>>(th);
    proj_mma<<<dim3(CBN / 128, 2), 256, proj_smem>>>(x, y);
    sort_kernel<<<CP * CB, 1024, sizeof(SortSmem)>>>();
    combine_mma<<<CBN / 128, 256, comb_smem>>>(x, out);
}

// round 15
// speedup vs baseline: 1.4494x; 1.4494x over previous
#include <cuda_runtime.h>
#include <cuda_pipeline.h>
#include <cuda_fp16.h>
#include <cstdint>

// Problem constants
#define CB   4
#define CN   16384
#define CD   128
#define CP   100
#define CKP  112         // K padding for combine (7 k16-steps)
#define CBN  (CB * CN)   // 65536 points

// ---------------------------------------------------------------------------
// Scratch (static __device__ arrays; .bss zeroed — pad regions stay zero)
// ---------------------------------------------------------------------------
__device__ __align__(16) __half g_xproj[(size_t)CP * CBN];  // x projections; later diff
__device__ __align__(16) __half g_yproj[(size_t)CP * CBN];  // y projections
__device__ __align__(16) __half g_thetaH[128 * CD];         // [p][d], rows p>=100 == 0
__device__ __align__(16) __half g_thetaTH[CD * 128];        // [d][p], cols p>=100 == 0

// ---------------------------------------------------------------------------
// m16n8k16 fp16 MMA, fp32 accumulate (baseline PTX, plain sm_103 OK).
// ---------------------------------------------------------------------------
__device__ __forceinline__ void mma_f16(float* d, const uint32_t* a, const uint32_t* b) {
    asm volatile(
        "mma.sync.aligned.m16n8k16.row.col.f32.f16.f16.f32 "
        "{%0,%1,%2,%3}, {%4,%5,%6,%7}, {%8,%9}, {%0,%1,%2,%3};"
        : "+f"(d[0]), "+f"(d[1]), "+f"(d[2]), "+f"(d[3])
        : "r"(a[0]), "r"(a[1]), "r"(a[2]), "r"(a[3]), "r"(b[0]), "r"(b[1]));
}

// Monotone 12-bit quantizer: 4096 bins over [-8, 8].
__device__ __forceinline__ int quant12(float v) {
    int q = __float2int_rn(fmaf(v, 256.0f, 2048.0f));
    return max(0, min(4095, q));
}
__device__ __forceinline__ unsigned int warp_incl_scan(unsigned int v) {
#pragma unroll
    for (int o = 1; o < 32; o <<= 1) {
        unsigned int n = __shfl_up_sync(0xffffffffu, v, o);
        if ((threadIdx.x & 31) >= o) v += n;
    }
    return v;
}

#define ST 136   // smem row stride in halves; frag-load banks: 4*grp+tig, conflict-free

// ---------------------------------------------------------------------------
// Kernel 1: normalize theta; emit [p][d] (proj B) and [d][p] (combine B) fp16.
// ---------------------------------------------------------------------------
__global__ void norm_kernel(const float* __restrict__ th) {
    int p = blockIdx.x, d = threadIdx.x;
    float v  = th[p * CD + d];
    float ss = v * v;
#pragma unroll
    for (int o = 16; o; o >>= 1) ss += __shfl_xor_sync(0xffffffffu, ss, o);
    __shared__ float ws[4];
    if ((d & 31) == 0) ws[d >> 5] = ss;
    __syncthreads();
    float tot = ws[0] + ws[1] + ws[2] + ws[3];
    __half h = __float2half(v / fmaxf(sqrtf(tot), 1e-12f));
    g_thetaH[p * CD + d]   = h;
    g_thetaTH[d * 128 + p] = h;
}

// ---------------------------------------------------------------------------
// Kernel 2: projections, fp16 m16n8k16 (R13 proven config).
// Tile: D[m(128) x p(128)] = X . Theta^T. Warp grid 2(m) x 4(p); warp tile
// 64x32; 8 k-steps. Frag loads batched bf-all + af-per-2ma (reg cap 128 ->
// 2 CTAs/SM).
// ---------------------------------------------------------------------------
__global__ __launch_bounds__(256, 2) void proj_mma(const float* __restrict__ x,
                                                   const float* __restrict__ y) {
    extern __shared__ __align__(16) __half sm[];
    __half* sA = sm;             // X     [m][d]  128 x ST
    __half* sB = sm + 128 * ST;  // theta [p][d]  128 x ST
    const float* __restrict__ src = blockIdx.y ? y : x;
    __half* __restrict__ dst      = blockIdx.y ? g_yproj : g_xproj;
    const int m0 = blockIdx.x * 128;
    const int t = threadIdx.x;

    // theta via cp.async (already fp16 in gmem); fire first
#pragma unroll
    for (int j = 0; j < 8; j++) {
        int i = t + 256 * j, r = i >> 4, c = i & 15;
        __pipeline_memcpy_async((char*)(sB + r * ST) + c * 16,
                                (const char*)(g_thetaH + r * CD) + c * 16, 16);
    }
    __pipeline_commit();
    // X with inline f32 -> f16 conversion
#pragma unroll
    for (int j = 0; j < 16; j++) {
        int i = t + 256 * j, r = i >> 5, c = i & 31;
        float4 v = *reinterpret_cast<const float4*>(src + (size_t)(m0 + r) * CD + c * 4);
        *reinterpret_cast<__half2*>(sA + r * ST + c * 4)     = __floats2half2_rn(v.x, v.y);
        *reinterpret_cast<__half2*>(sA + r * ST + c * 4 + 2) = __floats2half2_rn(v.z, v.w);
    }
    __pipeline_wait_prior(0);
    __syncthreads();

    const int w = t >> 5, lane = t & 31;
    const int wm = (w >> 2) * 64, wn = (w & 3) * 32;
    const int grp = lane >> 2, tig = lane & 3;

    float acc[4][4][4];
#pragma unroll
    for (int i = 0; i < 4; i++)
#pragma unroll
        for (int j = 0; j < 4; j++)
#pragma unroll
            for (int k = 0; k < 4; k++) acc[i][j][k] = 0.0f;

#pragma unroll
    for (int k0 = 0; k0 < 128; k0 += 16) {
        uint32_t bf[4][2];
#pragma unroll
        for (int na = 0; na < 4; na++) {
            const __half* bp = sB + (wn + na * 8 + grp) * ST + k0 + 2 * tig;
            bf[na][0] = *reinterpret_cast<const uint32_t*>(bp);
            bf[na][1] = *reinterpret_cast<const uint32_t*>(bp + 8);
        }
#pragma unroll
        for (int mh = 0; mh < 2; mh++) {     // 2 ma per batch: frags fit 128 regs
            uint32_t af[2][4];
#pragma unroll
            for (int mi = 0; mi < 2; mi++) {
                const __half* ap = sA + (wm + (2 * mh + mi) * 16 + grp) * ST + k0 + 2 * tig;
                af[mi][0] = *reinterpret_cast<const uint32_t*>(ap);
                af[mi][1] = *reinterpret_cast<const uint32_t*>(ap + 8 * ST);
                af[mi][2] = *reinterpret_cast<const uint32_t*>(ap + 8);
                af[mi][3] = *reinterpret_cast<const uint32_t*>(ap + 8 * ST + 8);
            }
#pragma unroll
            for (int mi = 0; mi < 2; mi++)
#pragma unroll
                for (int na = 0; na < 4; na++)
                    mma_f16(acc[2 * mh + mi][na], af[mi], bf[na]);
        }
    }

    // epilogue: D[m][p] -> dst[p*CBN + m] (half); skip pad cols p>=100
#pragma unroll
    for (int ma = 0; ma < 4; ma++) {
        int mg = m0 + wm + ma * 16 + grp;
#pragma unroll
        for (int na = 0; na < 4; na++) {
            int pp = wn + na * 8 + 2 * tig;
#pragma unroll
            for (int j = 0; j < 4; j++) {
                int p = pp + (j & 1);
                int m = mg + ((j >> 1) << 3);
                if (p < CP) dst[(size_t)p * CBN + m] = __float2half(acc[ma][na][j]);
            }
        }
    }
}

// ---------------------------------------------------------------------------
// Kernel 3: per-segment transport pairing via bucket/counting sort (12-bit),
// fp16 in/out, half2-vectorized passes (pair of adjacent elements per step:
// half the LDG/loop instructions, paired STG.32 diff stores).
// ---------------------------------------------------------------------------
#define NBIN 4096
struct SortSmem {
    unsigned int hx[NBIN];
    unsigned int hy[NBIN];
    __half       ysort[CN];
    unsigned int tmp[64];
};

__global__ __launch_bounds__(1024, 2) void sort_kernel() {
    extern __shared__ __align__(16) char smem_raw[];
    SortSmem& s = *reinterpret_cast<SortSmem*>(smem_raw);

    const int    t    = threadIdx.x;
    const int    lane = t & 31, wid = t >> 5;
    const size_t base = (size_t)blockIdx.x * CN;
    const uint32_t* __restrict__ xw = reinterpret_cast<const uint32_t*>(g_xproj + base);
    const uint32_t* __restrict__ yw = reinterpret_cast<const uint32_t*>(g_yproj + base);

#pragma unroll
    for (int i = t; i < NBIN; i += 1024) { s.hx[i] = 0; s.hy[i] = 0; }
    __syncthreads();

    // histogram pass: 2 elements per u32 load
#pragma unroll
    for (int j = 0; j < 8; j++) {
        int i2 = t + 1024 * j;
        uint32_t xv = xw[i2], yv = yw[i2];
        float2 xf = __half22float2(*reinterpret_cast<const __half2*>(&xv));
        float2 yf = __half22float2(*reinterpret_cast<const __half2*>(&yv));
        atomicAdd(&s.hx[quant12(xf.x)], 1u);
        atomicAdd(&s.hx[quant12(xf.y)], 1u);
        atomicAdd(&s.hy[quant12(yf.x)], 1u);
        atomicAdd(&s.hy[quant12(yf.y)], 1u);
    }
    __syncthreads();

    {   // dual in-place exclusive scan (4 bins per thread per histogram)
        const int b0 = t * 4;
        unsigned int ax[4], ay[4], sx = 0, sy = 0;
#pragma unroll
        for (int i = 0; i < 4; i++) {
            ax[i] = s.hx[b0 + i]; sx += ax[i];
            ay[i] = s.hy[b0 + i]; sy += ay[i];
        }
        unsigned int ix = warp_incl_scan(sx);
        unsigned int iy = warp_incl_scan(sy);
        if (lane == 31) { s.tmp[wid] = ix; s.tmp[32 + wid] = iy; }
        __syncthreads();
        if (wid == 0) {
            unsigned int vx = s.tmp[lane], vy = s.tmp[32 + lane];
            unsigned int jx = warp_incl_scan(vx), jy = warp_incl_scan(vy);
            s.tmp[lane]      = jx - vx;
            s.tmp[32 + lane] = jy - vy;
        }
        __syncthreads();
        unsigned int bx = s.tmp[wid] + ix - sx;
        unsigned int by = s.tmp[32 + wid] + iy - sy;
#pragma unroll
        for (int i = 0; i < 4; i++) {
            unsigned int c;
            c = ax[i]; s.hx[b0 + i] = bx; bx += c;
            c = ay[i]; s.hy[b0 + i] = by; by += c;
        }
    }
    __syncthreads();

    // place y into sorted order (atomic slot within bin), 2 per load
#pragma unroll
    for (int j = 0; j < 8; j++) {
        int i2 = t + 1024 * j;
        uint32_t yv = yw[i2];
        __half2 yh = *reinterpret_cast<const __half2*>(&yv);
        float2 yf = __half22float2(yh);
        unsigned int r0 = atomicAdd(&s.hy[quant12(yf.x)], 1u);
        unsigned int r1 = atomicAdd(&s.hy[quant12(yf.y)], 1u);
        s.ysort[r0] = __low2half(yh);
        s.ysort[r1] = __high2half(yh);
    }
    __syncthreads();

    // rank x; diff written back paired (one STG.32 per 2 elements)
#pragma unroll
    for (int j = 0; j < 8; j++) {
        int i2 = t + 1024 * j;
        uint32_t xv = xw[i2];
        float2 xf = __half22float2(*reinterpret_cast<const __half2*>(&xv));
        unsigned int r0 = atomicAdd(&s.hx[quant12(xf.x)], 1u);
        unsigned int r1 = atomicAdd(&s.hx[quant12(xf.y)], 1u);
        float d0 = __half2float(s.ysort[r0]) - xf.x;
        float d1 = __half2float(s.ysort[r1]) - xf.y;
        __half2 dh = __floats2half2_rn(d0, d1);
        reinterpret_cast<uint32_t*>(g_xproj + base)[i2] =
            *reinterpret_cast<const uint32_t*>(&dh);
    }
}

// ---------------------------------------------------------------------------
// Kernel 4: combine, fp16 m16n8k16 (R13 proven config).
// D[m(128) x d(128)] = diffT[m][p] . theta[p][d]; K = p padded to 112.
// diff tile transposed in-smem during staging; warp grid 2(m) x 4(d);
// frag loads bf-all + af-per-2ma. Epilogue fuses out = x + sc*D (fp32).
// ---------------------------------------------------------------------------
__global__ __launch_bounds__(256, 2) void combine_mma(const float* __restrict__ x,
                                                      float* __restrict__ out) {
    extern __shared__ __align__(16) __half sm[];
    __half* sA = sm;             // diff   [m][p]  128 x ST
    __half* sB = sm + 128 * ST;  // thetaT [d][p]  128 x ST
    const int m0 = blockIdx.x * 128;
    const int t = threadIdx.x;

#pragma unroll
    for (int j = 0; j < 8; j++) {
        int i = t + 256 * j, r = i >> 4, c = i & 15;
        __pipeline_memcpy_async((char*)(sB + r * ST) + c * 16,
                                (const char*)(g_thetaTH + r * 128) + c * 16, 16);
    }
    __pipeline_commit();
    // transpose-stage diff: half2 reads along m of one p-row -> 2 STS.16
#pragma unroll
    for (int j = 0; j < 25; j++) {
        int i = t + 256 * j;               // < 6400 = 100p x 64 mpairs
        int mp = i & 63, p = i >> 6;
        __half2 v = *reinterpret_cast<const __half2*>(g_xproj + (size_t)p * CBN + m0 + 2 * mp);
        sA[(2 * mp) * ST + p]     = __low2half(v);
        sA[(2 * mp + 1) * ST + p] = __high2half(v);
    }
    __half2 z2 = __float2half2_rn(0.0f);
#pragma unroll
    for (int j = 0; j < 3; j++) {          // zero pad p in [100,112): 6 pairs x 128 m
        int i = t + 256 * j;               // < 768
        int m = i & 127, q = i >> 7;
        *reinterpret_cast<__half2*>(sA + m * ST + 100 + 2 * q) = z2;
    }
    __pipeline_wait_prior(0);
    __syncthreads();

    const int w = t >> 5, lane = t & 31;
    const int wm = (w >> 2) * 64, wn = (w & 3) * 32;
    const int grp = lane >> 2, tig = lane & 3;

    float acc[4][4][4];
#pragma unroll
    for (int i = 0; i < 4; i++)
#pragma unroll
        for (int j = 0; j < 4; j++)
#pragma unroll
            for (int k = 0; k < 4; k++) acc[i][j][k] = 0.0f;

#pragma unroll
    for (int k0 = 0; k0 < CKP; k0 += 16) {
        uint32_t bf[4][2];
#pragma unroll
        for (int na = 0; na < 4; na++) {
            const __half* bp = sB + (wn + na * 8 + grp) * ST + k0 + 2 * tig;
            bf[na][0] = *reinterpret_cast<const uint32_t*>(bp);
            bf[na][1] = *reinterpret_cast<const uint32_t*>(bp + 8);
        }
#pragma unroll
        for (int mh = 0; mh < 2; mh++) {
            uint32_t af[2][4];
#pragma unroll
            for (int mi = 0; mi < 2; mi++) {
                const __half* ap = sA + (wm + (2 * mh + mi) * 16 + grp) * ST + k0 + 2 * tig;
                af[mi][0] = *reinterpret_cast<const uint32_t*>(ap);
                af[mi][1] = *reinterpret_cast<const uint32_t*>(ap + 8 * ST);
                af[mi][2] = *reinterpret_cast<const uint32_t*>(ap + 8);
                af[mi][3] = *reinterpret_cast<const uint32_t*>(ap + 8 * ST + 8);
            }
#pragma unroll
            for (int mi = 0; mi < 2; mi++)
#pragma unroll
                for (int na = 0; na < 4; na++)
                    mma_f16(acc[2 * mh + mi][na], af[mi], bf[na]);
        }
    }

    // epilogue: out[m][d] = x[m][d] + sc*D[m][d], float2 stores
    const float sc = 1.0f / (float)CP;
#pragma unroll
    for (int ma = 0; ma < 4; ma++) {
#pragma unroll
        for (int j2 = 0; j2 < 2; j2++) {
            size_t row = (size_t)(m0 + wm + ma * 16 + grp + j2 * 8) * CD;
#pragma unroll
            for (int na = 0; na < 4; na++) {
                int d = wn + na * 8 + 2 * tig;
                float2 xv = *reinterpret_cast<const float2*>(&x[row + d]);
                float2 o  = make_float2(fmaf(acc[ma][na][j2 * 2],     sc, xv.x),
                                        fmaf(acc[ma][na][j2 * 2 + 1], sc, xv.y));
                *reinterpret_cast<float2*>(&out[row + d]) = o;
            }
        }
    }
}

// ---------------------------------------------------------------------------
// Entry point
// ---------------------------------------------------------------------------
extern "C" void kernel_launch(void* const* d_in, const int* in_sizes, int n_in,
                              void* d_out, int out_size) {
    const float* x   = (const float*)d_in[0];
    const float* y   = (const float*)d_in[1];
    const float* th  = (const float*)d_in[2];
    float*       out = (float*)d_out;

    const int gemm_smem = 2 * 128 * ST * 2;   // 69,632 B
    cudaFuncSetAttribute(sort_kernel, cudaFuncAttributeMaxDynamicSharedMemorySize,
                         (int)sizeof(SortSmem));
    cudaFuncSetAttribute(proj_mma, cudaFuncAttributeMaxDynamicSharedMemorySize, gemm_smem);
    cudaFuncSetAttribute(combine_mma, cudaFuncAttributeMaxDynamicSharedMemorySize, gemm_smem);

    norm_kernel<<<CP, CD>>>(th);
    proj_mma<<<dim3(CBN / 128, 2), 256, gemm_smem>>>(x, y);
    sort_kernel<<<CP * CB, 1024, sizeof(SortSmem)>>>();
    combine_mma<<<CBN / 128, 256, gemm_smem>>>(x, out);
}